// round 3
// baseline (speedup 1.0000x reference)
#include <cuda_runtime.h>
#include <math.h>

// ---------------- problem constants ----------------
#define KK   16
#define TT   40
#define BB   16
#define NN   32
#define BN   512            // BB*NN
#define KBN  8192           // KK*BN
#define HH2  80             // fmap H=W=80
#define C1   16
#define C2   32
#define NBIN 36

// ---------------- device scratch (allowed: __device__ globals) -------------
__device__ float g_conv1[BB*C1*HH2*HH2];            // (b,oc,y,x)
__device__ float g_fmap [BB*HH2*HH2*C2];            // (b,y,x,c)  channel-last
__device__ float g_lhalf[KK*TT*BN*48];              // per (k,t,row) first 48 of x
__device__ unsigned char g_bins[KK*TT*BN*NN];       // neighbor bin
__device__ float g_wgt  [KK*TT*BN*NN];              // mask/cnt weight
__device__ float g_WscfT[1728*48];                  // transposed fc_scf_w
__device__ float g_HW   [BB*NN*NBIN*48];            // per-step table
__device__ float g_gh   [KBN*144];                  // h @ W_hh^T + b_hh
__device__ float g_h    [2][KBN*48];                // ping-pong hidden
__device__ float g_score[KBN];                      // running score dot

// ---------------- conv1: naive, (b,oc,y,x), stride2 pad2, relu ------------
__global__ void conv1_kernel(const float* __restrict__ img,
                             const float* __restrict__ w,
                             const float* __restrict__ bias) {
    __shared__ float sW[1600];
    __shared__ float sB[16];
    for (int i = threadIdx.x; i < 1600; i += 256) sW[i] = w[i];
    if (threadIdx.x < 16) sB[threadIdx.x] = bias[threadIdx.x];
    __syncthreads();
    int idx = blockIdx.x*256 + threadIdx.x;          // 1,638,400 exact
    int x = idx % HH2; int y = (idx/HH2) % HH2;
    int oc = (idx/(HH2*HH2)) % C1; int b = idx/(HH2*HH2*C1);
    float acc = sB[oc];
    for (int ic = 0; ic < 4; ic++) {
        for (int ky = 0; ky < 5; ky++) {
            int iy = 2*y - 2 + ky;
            if (iy < 0 || iy >= 160) continue;
            const float* ip = img + ((b*4+ic)*160 + iy)*160;
            const float* wp = sW + (oc*4+ic)*25 + ky*5;
            #pragma unroll
            for (int kx = 0; kx < 5; kx++) {
                int ix = 2*x - 2 + kx;
                if (ix < 0 || ix >= 160) continue;
                acc += ip[ix] * wp[kx];
            }
        }
    }
    g_conv1[idx] = fmaxf(acc, 0.f);
}

// ---------------- conv2: smem-tiled, stride1 pad2, relu, channel-last -----
__global__ void conv2_kernel(const float* __restrict__ w2,
                             const float* __restrict__ b2) {
    __shared__ float sIn[16*20*20];   // 6400 floats
    __shared__ float sW [8*16*25];    // 3200 floats
    int blk = blockIdx.x;                       // 16*25*4 = 1600
    int ocg = blk % 4; int tile = (blk/4) % 25; int b = blk/100;
    int ty0 = (tile/5)*16, tx0 = (tile%5)*16;
    int tid = threadIdx.x;
    for (int i = tid; i < 6400; i += 256) {
        int ic = i/400; int rem = i%400; int ly = rem/20, lx = rem%20;
        int iy = ty0 + ly - 2, ix = tx0 + lx - 2;
        sIn[i] = (iy>=0 && iy<HH2 && ix>=0 && ix<HH2)
                 ? g_conv1[((b*C1+ic)*HH2+iy)*HH2+ix] : 0.f;
    }
    for (int i = tid; i < 3200; i += 256) sW[i] = w2[ocg*3200 + i];
    __syncthreads();
    int ty = tid/16, tx = tid%16;
    for (int ocl = 0; ocl < 8; ocl++) {
        int oc = ocg*8 + ocl;
        float acc = b2[oc];
        for (int ic = 0; ic < 16; ic++) {
            const float* ip = sIn + ic*400;
            const float* wp = sW + ocl*400 + ic*25;
            #pragma unroll
            for (int ky = 0; ky < 5; ky++)
                #pragma unroll
                for (int kx = 0; kx < 5; kx++)
                    acc += ip[(ty+ky)*20 + (tx+kx)] * wp[ky*5+kx];
        }
        g_fmap[((b*HH2 + ty0+ty)*HH2 + tx0+tx)*C2 + oc] = fmaxf(acc, 0.f);
    }
}

// ---------------- transpose fc_scf_w (48,1728) -> (1728,48) ---------------
__global__ void transposeW_kernel(const float* __restrict__ w) {
    int idx = blockIdx.x*256 + threadIdx.x;    // 82944 exact
    int c = idx / 1728; int oh = idx % 1728;
    g_WscfT[oh*48 + c] = w[idx];
}

// ---------------- lhalf: feature gather + velocity FC ---------------------
__global__ void lhalf_kernel(const float* __restrict__ y_path,
                             const float* __restrict__ cur_loc,
                             const float* __restrict__ fvw,
                             const float* __restrict__ fvb) {
    int row = blockIdx.x*256 + threadIdx.x;    // 327680 exact
    int kt = row / BN, i2 = row % BN;
    int t = kt % TT;
    int b = i2 >> 5;
    float px = y_path[(kt*BN + i2)*2 + 0];
    float py = y_path[(kt*BN + i2)*2 + 1];
    int u = 40 - (int)py; u = min(max(u,0), HH2-1);
    int v = (int)px;      v = min(max(v,0), HH2-1);
    const float* f = g_fmap + ((b*HH2+u)*HH2+v)*C2;
    float* o = g_lhalf + row*48;
    #pragma unroll
    for (int c = 0; c < 32; c++) o[c] = f[c];
    float pvx, pvy;
    if (t == 0) { pvx = cur_loc[i2*2]; pvy = cur_loc[i2*2+1]; }
    else { pvx = y_path[((kt-1)*BN+i2)*2]; pvy = y_path[((kt-1)*BN+i2)*2+1]; }
    float vx = (px - pvx)*10.f, vy = (py - pvy)*10.f;
    #pragma unroll
    for (int c = 0; c < 16; c++) o[32+c] = fvb[c] + vx*fvw[c*2] + vy*fvw[c*2+1];
}

// ---------------- bins/weights for all (k,t,b,j) ---------------------------
__global__ void bins_kernel(const float* __restrict__ y_path) {
    __shared__ float sP[4][NN][2];
    int tid = threadIdx.x;
    int g = tid >> 5, j = tid & 31;
    int grp = blockIdx.x*4 + g;                // 10240 = KK*TT*BB exact
    int b = grp % BB; int kt = grp / BB;
    int rowbase = kt*BN + b*NN;
    sP[g][j][0] = y_path[(rowbase+j)*2];
    sP[g][j][1] = y_path[(rowbase+j)*2+1];
    __syncwarp();
    float pjx = sP[g][j][0], pjy = sP[g][j][1];
    unsigned char binloc[NN];
    int cnt[NBIN];
    #pragma unroll
    for (int o = 0; o < NBIN; o++) cnt[o] = 0;
    unsigned int maskbits = 0;
    const float R_STEP  = (float)(3.5/6.0);
    const float TH_STEP = (float)(6.283185307179586/6.0);
    for (int n2 = 0; n2 < NN; n2++) {
        float dx = sP[g][n2][0] - pjx;
        float dy = sP[g][n2][1] - pjy;
        float dist = sqrtf(dx*dx + dy*dy);
        bool m = (n2 != j) && (dist >= 0.5f) && (dist <= 4.0f);
        float dc = dist < 1e-10f ? 1e-10f : dist;
        float ct = acosf(fminf(fmaxf(dx/dc, -1.f), 1.f));
        float theta = (dy < -0.01f) ? (6.2831853071795864f - ct) : ct;
        int ub = (int)((dist - 0.5f)/R_STEP); ub = min(max(ub,0),5);
        int vb = (int)(theta/TH_STEP);        vb = min(max(vb,0),5);
        int bin = ub*6 + vb;
        binloc[n2] = (unsigned char)bin;
        if (m) { maskbits |= (1u<<n2); cnt[bin]++; }
    }
    int out0 = (rowbase + j)*NN;
    for (int n2 = 0; n2 < NN; n2++) {
        bool m = (maskbits >> n2) & 1u;
        g_bins[out0+n2] = binloc[n2];
        g_wgt [out0+n2] = m ? (1.f/(float)cnt[binloc[n2]]) : 0.f;
    }
}

// ---------------- init h0 and score ----------------------------------------
__global__ void init_kernel(const float* __restrict__ hx) {
    int idx = blockIdx.x*256 + threadIdx.x;    // 401408 exact
    if (idx < KBN*48) g_h[0][idx] = hx[idx % (BN*48)];
    else g_score[idx - KBN*48] = 0.f;
}

// ---------------- step A: HW table + gh -------------------------------------
__global__ void stepA_kernel(const float* __restrict__ whh,
                             const float* __restrict__ bhh, int cur) {
    __shared__ float sm[10752];
    const float* h = g_h[cur];
    int blk = blockIdx.x, tid = threadIdx.x;
    if (blk < 144) {                            // HW: 16 b x 9 o-groups(4 each)
        int b = blk / 9, og = blk % 9;
        float* sWT = sm;            // 192*48 = 9216
        float* sHn = sm + 9216;     // 32*48  = 1536
        const float* src = g_WscfT + og*192*48;
        for (int i = tid; i < 9216; i += 256) sWT[i] = src[i];
        const float* hsrc = h + b*NN*48;        // Hn = h[:512] slice
        for (int i = tid; i < 1536; i += 256) sHn[i] = hsrc[i];
        __syncthreads();
        for (int out = tid; out < 6144; out += 256) {
            int c = out % 48; int rest = out / 48;
            int oo = rest % 4; int n2 = rest / 4;
            float acc = 0.f;
            const float* hn = sHn + n2*48;
            const float* wt = sWT + oo*48*48 + c;
            #pragma unroll 8
            for (int hh = 0; hh < 48; hh++) acc += hn[hh] * wt[hh*48];
            g_HW[((b*NN+n2)*NBIN + og*4+oo)*48 + c] = acc;
        }
    } else {                                    // gh: 128 blocks x 64 rows
        int blk2 = blk - 144;
        float* sWhh = sm;            // 144*48 = 6912
        float* sH   = sm + 6912;     // 64*48  = 3072
        for (int i = tid; i < 6912; i += 256) sWhh[i] = whh[i];
        int r0 = blk2*64;
        const float* hsrc = h + r0*48;
        for (int i = tid; i < 3072; i += 256) sH[i] = hsrc[i];
        __syncthreads();
        for (int out = tid; out < 9216; out += 256) {
            int c = out % 144; int r = out / 144;
            float acc = bhh[c];
            const float* hr = sH + r*48;
            const float* wc = sWhh + c*48;
            #pragma unroll 8
            for (int hh = 0; hh < 48; hh++) acc += hr[hh]*wc[hh];
            g_gh[(r0+r)*144 + c] = acc;
        }
    }
}

// ---------------- step B: rhalf + gi + GRU + score -------------------------
__global__ void stepB_kernel(const float* __restrict__ wih,
                             const float* __restrict__ bih,
                             const float* __restrict__ scfb,
                             const float* __restrict__ scw,
                             int t, int cur) {
    extern __shared__ float sm[];
    float* sWih = sm;                 // 13824
    float* sX   = sWih + 13824;       // 16*96
    float* sGi  = sX   + 1536;        // 16*144
    float* sWgt = sGi  + 2304;        // 16*32
    float* sSc  = sWgt + 512;         // 16*48
    unsigned char* sBin = (unsigned char*)(sSc + 768);  // 512 B
    const float* h  = g_h[cur];
    float* hnew     = g_h[1-cur];
    int tid = threadIdx.x;
    int r0  = blockIdx.x * 16;                  // 512 blocks
    for (int i = tid; i < 13824; i += 256) sWih[i] = wih[i];
    for (int i = tid; i < 512; i += 256) {
        int lr = i / 32, n2 = i % 32;
        int row = r0 + lr;
        int k = row >> 9; int i2 = row & 511;
        int gidx = ((k*TT + t)*BN + i2)*NN + n2;
        sWgt[i] = g_wgt[gidx];
        sBin[i] = g_bins[gidx];
    }
    __syncthreads();
    // phase 1: x = [lhalf, rhalf]
    for (int out = tid; out < 768; out += 256) {
        int lr = out / 48, c = out % 48;
        int row = r0 + lr;
        int k = row >> 9, i2 = row & 511, b = i2 >> 5;
        sX[lr*96 + c] = g_lhalf[((k*TT+t)*BN + i2)*48 + c];
        float acc = scfb[c];
        const float* hwb = g_HW + b*NN*NBIN*48;
        const float* wv  = sWgt + lr*32;
        const unsigned char* bv = sBin + lr*32;
        #pragma unroll 4
        for (int n2 = 0; n2 < NN; n2++) {
            float w = wv[n2];
            if (w != 0.f) acc += w * hwb[(n2*NBIN + bv[n2])*48 + c];
        }
        sX[lr*96 + 48 + c] = acc;
    }
    __syncthreads();
    // phase 2: gi = x @ W_ih^T + b_ih
    for (int out = tid; out < 2304; out += 256) {
        int lr = out / 144, c = out % 144;
        float acc = bih[c];
        const float* x = sX + lr*96;
        const float* w = sWih + c*96;
        #pragma unroll 8
        for (int m = 0; m < 96; m++) acc += x[m]*w[m];
        sGi[lr*144 + c] = acc;
    }
    __syncthreads();
    // phase 3: GRU elementwise + score partials
    for (int out = tid; out < 768; out += 256) {
        int lr = out / 48, c = out % 48;
        int row = r0 + lr;
        const float* gh = g_gh + row*144;
        float r  = 1.f/(1.f + expf(-(sGi[lr*144 + c]      + gh[c])));
        float z  = 1.f/(1.f + expf(-(sGi[lr*144 + 48 + c] + gh[48+c])));
        float nn = tanhf(sGi[lr*144 + 96 + c] + r*gh[96+c]);
        float hv = (1.f - z)*nn + z*h[row*48 + c];
        hnew[row*48 + c] = hv;
        sSc[lr*48 + c] = hv * scw[c];
    }
    __syncthreads();
    if (tid < 16) {
        float s = 0.f;
        #pragma unroll
        for (int c = 0; c < 48; c++) s += sSc[tid*48 + c];
        g_score[r0 + tid] += s;
    }
}

// ---------------- final: delta_y + score -----------------------------------
__global__ void final_kernel(const float* __restrict__ dyw,
                             const float* __restrict__ dyb,
                             const float* __restrict__ scb,
                             float* __restrict__ out, int cur) {
    const float* h = g_h[cur];
    int idx = blockIdx.x*256 + threadIdx.x;    // 663552 exact
    if (idx < KBN*80) {
        int row = idx / 80, c = idx % 80;
        float acc = dyb[c];
        const float* hr = h + row*48;
        const float* w  = dyw + c*48;
        #pragma unroll 8
        for (int hh = 0; hh < 48; hh++) acc += hr[hh]*w[hh];
        int k = row >> 9, i2 = row & 511;
        int d = c / 40, tt = c % 40;
        out[((k*TT + tt)*BN + i2)*2 + d] = acc;
    } else {
        int row = idx - KBN*80;
        out[KBN*80 + row] = g_score[row] + 40.f*scb[0];
    }
}

// ---------------- launcher ---------------------------------------------------
extern "C" void kernel_launch(void* const* d_in, const int* in_sizes, int n_in,
                              void* d_out, int out_size) {
    const float* hx      = (const float*)d_in[0];
    const float* cur_loc = (const float*)d_in[1];
    const float* y_path  = (const float*)d_in[2];
    const float* image   = (const float*)d_in[3];
    const float* c1w     = (const float*)d_in[4];
    const float* c1b     = (const float*)d_in[5];
    const float* c2w     = (const float*)d_in[6];
    const float* c2b     = (const float*)d_in[7];
    const float* fvw     = (const float*)d_in[8];
    const float* fvb     = (const float*)d_in[9];
    const float* scfw    = (const float*)d_in[10];
    const float* scfb    = (const float*)d_in[11];
    const float* wih     = (const float*)d_in[12];
    const float* whh     = (const float*)d_in[13];
    const float* bih     = (const float*)d_in[14];
    const float* bhh     = (const float*)d_in[15];
    const float* dyw     = (const float*)d_in[16];
    const float* dyb     = (const float*)d_in[17];
    const float* scw     = (const float*)d_in[18];
    const float* scb     = (const float*)d_in[19];

    const int SMEMB = (13824 + 1536 + 2304 + 512 + 768)*4 + 512;  // 76288 B
    cudaFuncSetAttribute(stepB_kernel,
                         cudaFuncAttributeMaxDynamicSharedMemorySize, SMEMB);

    conv1_kernel     <<<6400, 256>>>(image, c1w, c1b);
    conv2_kernel     <<<1600, 256>>>(c2w, c2b);
    transposeW_kernel<<<324,  256>>>(scfw);
    lhalf_kernel     <<<1280, 256>>>(y_path, cur_loc, fvw, fvb);
    bins_kernel      <<<2560, 128>>>(y_path);
    init_kernel      <<<1568, 256>>>(hx);

    int cur = 0;
    for (int t = 0; t < TT; t++) {
        stepA_kernel<<<272, 256>>>(whh, bhh, cur);
        stepB_kernel<<<512, 256, SMEMB>>>(wih, bih, scfb, scw, t, cur);
        cur ^= 1;
    }
    final_kernel<<<2592, 256>>>(dyw, dyb, scb, (float*)d_out, cur);
}

// round 4
// speedup vs baseline: 4.2437x; 4.2437x over previous
#include <cuda_runtime.h>
#include <math.h>

// ---------------- problem constants ----------------
#define KK   16
#define TT   40
#define BB   16
#define NN   32
#define BN   512            // BB*NN
#define KBN  8192           // KK*BN
#define HH2  80             // fmap H=W=80
#define C1   16
#define C2   32
#define NBIN 36

// ---------------- device scratch ----------------
__device__ float g_conv1[BB*C1*HH2*HH2];            // (b,oc,y,x)
__device__ float g_fmap [BB*HH2*HH2*C2];            // (b,y,x,c)
__device__ float g_lhalf[KK*TT*BN*48];              // first 48 of x per (kt,row)
__device__ float g_gil  [KK*TT*BN*144];             // lhalf @ Wih[:, :48]^T + bih
__device__ unsigned char g_bins[KK*TT*BN*NN];
__device__ float g_wgt  [KK*TT*BN*NN];
__device__ float g_WscfT[1728*48];
__device__ float g_HW   [BB*NN*NBIN*48];
__device__ float g_gh   [KBN*144];
__device__ float g_h    [2][KBN*48];
__device__ float g_score[KBN];

// ---------------- conv1 ----------------
__global__ void conv1_kernel(const float* __restrict__ img,
                             const float* __restrict__ w,
                             const float* __restrict__ bias) {
    __shared__ float sW[1600];
    __shared__ float sB[16];
    for (int i = threadIdx.x; i < 1600; i += 256) sW[i] = w[i];
    if (threadIdx.x < 16) sB[threadIdx.x] = bias[threadIdx.x];
    __syncthreads();
    int idx = blockIdx.x*256 + threadIdx.x;          // 1,638,400 exact
    int x = idx % HH2; int y = (idx/HH2) % HH2;
    int oc = (idx/(HH2*HH2)) % C1; int b = idx/(HH2*HH2*C1);
    float acc = sB[oc];
    for (int ic = 0; ic < 4; ic++) {
        for (int ky = 0; ky < 5; ky++) {
            int iy = 2*y - 2 + ky;
            if (iy < 0 || iy >= 160) continue;
            const float* ip = img + ((b*4+ic)*160 + iy)*160;
            const float* wp = sW + (oc*4+ic)*25 + ky*5;
            #pragma unroll
            for (int kx = 0; kx < 5; kx++) {
                int ix = 2*x - 2 + kx;
                if (ix < 0 || ix >= 160) continue;
                acc += ip[ix] * wp[kx];
            }
        }
    }
    g_conv1[idx] = fmaxf(acc, 0.f);
}

// ---------------- conv2 ----------------
__global__ void conv2_kernel(const float* __restrict__ w2,
                             const float* __restrict__ b2) {
    __shared__ float sIn[16*20*20];
    __shared__ float sW [8*16*25];
    int blk = blockIdx.x;                       // 1600
    int ocg = blk % 4; int tile = (blk/4) % 25; int b = blk/100;
    int ty0 = (tile/5)*16, tx0 = (tile%5)*16;
    int tid = threadIdx.x;
    for (int i = tid; i < 6400; i += 256) {
        int ic = i/400; int rem = i%400; int ly = rem/20, lx = rem%20;
        int iy = ty0 + ly - 2, ix = tx0 + lx - 2;
        sIn[i] = (iy>=0 && iy<HH2 && ix>=0 && ix<HH2)
                 ? g_conv1[((b*C1+ic)*HH2+iy)*HH2+ix] : 0.f;
    }
    for (int i = tid; i < 3200; i += 256) sW[i] = w2[ocg*3200 + i];
    __syncthreads();
    int ty = tid/16, tx = tid%16;
    for (int ocl = 0; ocl < 8; ocl++) {
        int oc = ocg*8 + ocl;
        float acc = b2[oc];
        for (int ic = 0; ic < 16; ic++) {
            const float* ip = sIn + ic*400;
            const float* wp = sW + ocl*400 + ic*25;
            #pragma unroll
            for (int ky = 0; ky < 5; ky++)
                #pragma unroll
                for (int kx = 0; kx < 5; kx++)
                    acc += ip[(ty+ky)*20 + (tx+kx)] * wp[ky*5+kx];
        }
        g_fmap[((b*HH2 + ty0+ty)*HH2 + tx0+tx)*C2 + oc] = fmaxf(acc, 0.f);
    }
}

// ---------------- transpose fc_scf_w ----------------
__global__ void transposeW_kernel(const float* __restrict__ w) {
    int idx = blockIdx.x*256 + threadIdx.x;    // 82944 exact
    int c = idx / 1728; int oh = idx % 1728;
    g_WscfT[oh*48 + c] = w[idx];
}

// ---------------- lhalf (coalesced: thread = (row,c)) ----------------
__global__ void lhalf_kernel(const float* __restrict__ y_path,
                             const float* __restrict__ cur_loc,
                             const float* __restrict__ fvw,
                             const float* __restrict__ fvb) {
    int idx = blockIdx.x*256 + threadIdx.x;    // 15,728,640 exact
    int c = idx % 48; int row = idx / 48;
    int kt = row / BN, i2 = row % BN;
    int t = kt % TT; int b = i2 >> 5;
    float px = y_path[row*2], py = y_path[row*2+1];
    float out;
    if (c < 32) {
        int u = 40 - (int)py; u = min(max(u,0), HH2-1);
        int v = (int)px;      v = min(max(v,0), HH2-1);
        out = g_fmap[((b*HH2+u)*HH2+v)*C2 + c];
    } else {
        int cc = c - 32;
        float pvx, pvy;
        if (t == 0) { pvx = cur_loc[i2*2]; pvy = cur_loc[i2*2+1]; }
        else { pvx = y_path[(row-BN)*2]; pvy = y_path[(row-BN)*2+1]; }
        out = fvb[cc] + (px-pvx)*10.f*fvw[cc*2] + (py-pvy)*10.f*fvw[cc*2+1];
    }
    g_lhalf[idx] = out;
}

// ---------------- gil = lhalf @ Wih[:, :48]^T + bih ----------------
__global__ void gil_kernel(const float* __restrict__ wih,
                           const float* __restrict__ bih) {
    __shared__ float sA[64*48];     // 3072
    __shared__ float sW[48*145];    // 6960 (transposed, padded odd)
    __shared__ float sB[144];
    int tid = threadIdx.x;
    int r0 = blockIdx.x * 64;                   // 5120 blocks
    for (int i = tid; i < 3072; i += 256) sA[i] = g_lhalf[r0*48 + i];
    for (int i = tid; i < 6912; i += 256) {
        int c = i / 48, m = i % 48;
        sW[m*145 + c] = wih[c*96 + m];
    }
    if (tid < 144) sB[tid] = bih[tid];
    __syncthreads();
    for (int it = tid; it < 576; it += 256) {   // (cg36, lrg16), 4c x 4row
        int cg = it % 36, lrg = it / 36;
        float acc[4][4];
        #pragma unroll
        for (int j = 0; j < 4; j++) {
            float bv = sB[cg + 36*j];
            #pragma unroll
            for (int i = 0; i < 4; i++) acc[i][j] = bv;
        }
        for (int m = 0; m < 48; m++) {
            float av[4], wv[4];
            #pragma unroll
            for (int i = 0; i < 4; i++) av[i] = sA[(lrg*4+i)*48 + m];
            #pragma unroll
            for (int j = 0; j < 4; j++) wv[j] = sW[m*145 + cg + 36*j];
            #pragma unroll
            for (int i = 0; i < 4; i++)
                #pragma unroll
                for (int j = 0; j < 4; j++) acc[i][j] += av[i]*wv[j];
        }
        #pragma unroll
        for (int i = 0; i < 4; i++)
            #pragma unroll
            for (int j = 0; j < 4; j++)
                g_gil[(r0 + lrg*4+i)*144 + cg + 36*j] = acc[i][j];
    }
}

// ---------------- bins ----------------
__global__ void bins_kernel(const float* __restrict__ y_path) {
    __shared__ float sP[4][NN][2];
    int tid = threadIdx.x;
    int g = tid >> 5, j = tid & 31;
    int grp = blockIdx.x*4 + g;                // 10240 exact
    int b = grp % BB; int kt = grp / BB;
    int rowbase = kt*BN + b*NN;
    sP[g][j][0] = y_path[(rowbase+j)*2];
    sP[g][j][1] = y_path[(rowbase+j)*2+1];
    __syncwarp();
    float pjx = sP[g][j][0], pjy = sP[g][j][1];
    unsigned char binloc[NN];
    int cnt[NBIN];
    #pragma unroll
    for (int o = 0; o < NBIN; o++) cnt[o] = 0;
    unsigned int maskbits = 0;
    const float R_STEP  = (float)(3.5/6.0);
    const float TH_STEP = (float)(6.283185307179586/6.0);
    for (int n2 = 0; n2 < NN; n2++) {
        float dx = sP[g][n2][0] - pjx;
        float dy = sP[g][n2][1] - pjy;
        float dist = sqrtf(dx*dx + dy*dy);
        bool m = (n2 != j) && (dist >= 0.5f) && (dist <= 4.0f);
        float dc = dist < 1e-10f ? 1e-10f : dist;
        float ct = acosf(fminf(fmaxf(dx/dc, -1.f), 1.f));
        float theta = (dy < -0.01f) ? (6.2831853071795864f - ct) : ct;
        int ub = (int)((dist - 0.5f)/R_STEP); ub = min(max(ub,0),5);
        int vb = (int)(theta/TH_STEP);        vb = min(max(vb,0),5);
        int bin = ub*6 + vb;
        binloc[n2] = (unsigned char)bin;
        if (m) { maskbits |= (1u<<n2); cnt[bin]++; }
    }
    int out0 = (rowbase + j)*NN;
    for (int n2 = 0; n2 < NN; n2++) {
        bool m = (maskbits >> n2) & 1u;
        g_bins[out0+n2] = binloc[n2];
        g_wgt [out0+n2] = m ? (1.f/(float)cnt[binloc[n2]]) : 0.f;
    }
}

// ---------------- init ----------------
__global__ void init_kernel(const float* __restrict__ hx) {
    int idx = blockIdx.x*256 + threadIdx.x;    // 401408 exact
    if (idx < KBN*48) g_h[0][idx] = hx[idx % (BN*48)];
    else g_score[idx - KBN*48] = 0.f;
}

// ---------------- step A: HW table + gh (conflict-free, reg-tiled) --------
__global__ void stepA_kernel(const float* __restrict__ whh,
                             const float* __restrict__ bhh, int cur) {
    __shared__ float sm[10752];
    const float* h = g_h[cur];
    int blk = blockIdx.x, tid = threadIdx.x;
    if (blk < 144) {                            // HW: 16 b x 9 o-groups(4 each)
        float* sWT = sm;            // 192*48 = 9216
        float* sHn = sm + 9216;     // 32*48  = 1536
        int b = blk / 9, og = blk % 9;
        const float* src = g_WscfT + og*192*48;
        for (int i = tid; i < 9216; i += 256) sWT[i] = src[i];
        const float* hs = h + b*NN*48;
        for (int i = tid; i < 1536; i += 256) sHn[i] = hs[i];
        __syncthreads();
        // items (cg24, oo4, n2g8): each 2c x 4n2
        for (int it = tid; it < 768; it += 256) {
            int cg = it % 24; int oo = (it/24) & 3; int n2g = it / 96;
            float acc[4][2];
            #pragma unroll
            for (int i = 0; i < 4; i++) { acc[i][0] = 0.f; acc[i][1] = 0.f; }
            const float* wt = sWT + oo*2304;
            for (int hh = 0; hh < 48; hh++) {
                float w0 = wt[hh*48 + cg];
                float w1 = wt[hh*48 + cg + 24];
                #pragma unroll
                for (int i = 0; i < 4; i++) {
                    float hv = sHn[(n2g*4+i)*48 + hh];
                    acc[i][0] += hv*w0; acc[i][1] += hv*w1;
                }
            }
            #pragma unroll
            for (int i = 0; i < 4; i++) {
                int base = ((b*NN + n2g*4+i)*NBIN + og*4 + oo)*48;
                g_HW[base + cg]      = acc[i][0];
                g_HW[base + cg + 24] = acc[i][1];
            }
        }
    } else {                                    // gh: 128 blocks x 64 rows
        float* sW  = sm;             // 144*49 = 7056 (padded)
        float* sH  = sm + 7056;      // 3072
        float* sBh = sm + 10128;     // 144
        int r0 = (blk - 144) * 64;
        for (int i = tid; i < 6912; i += 256) sW[(i/48)*49 + (i%48)] = whh[i];
        const float* hs = h + r0*48;
        for (int i = tid; i < 3072; i += 256) sH[i] = hs[i];
        if (tid < 144) sBh[tid] = bhh[tid];
        __syncthreads();
        // items (cg36, rg16): each 4c x 4row, interleaved c
        for (int it = tid; it < 576; it += 256) {
            int cg = it % 36, rg = it / 36;
            float acc[4][4];
            #pragma unroll
            for (int j = 0; j < 4; j++) {
                float bv = sBh[cg + 36*j];
                #pragma unroll
                for (int i = 0; i < 4; i++) acc[i][j] = bv;
            }
            for (int hh = 0; hh < 48; hh++) {
                float hv[4], wv[4];
                #pragma unroll
                for (int i = 0; i < 4; i++) hv[i] = sH[(rg*4+i)*48 + hh];
                #pragma unroll
                for (int j = 0; j < 4; j++) wv[j] = sW[(cg+36*j)*49 + hh];
                #pragma unroll
                for (int i = 0; i < 4; i++)
                    #pragma unroll
                    for (int j = 0; j < 4; j++) acc[i][j] += hv[i]*wv[j];
            }
            #pragma unroll
            for (int i = 0; i < 4; i++)
                #pragma unroll
                for (int j = 0; j < 4; j++)
                    g_gh[(r0 + rg*4+i)*144 + cg + 36*j] = acc[i][j];
        }
    }
}

// ---------------- step B: rhalf + gi(+gil) + GRU + score -------------------
__global__ void stepB_kernel(const float* __restrict__ wih,
                             const float* __restrict__ scfb,
                             const float* __restrict__ scw,
                             int t, int cur) {
    __shared__ float sWr[48*145];     // 6960 (transposed r-half, padded)
    __shared__ float sR [16*48];      // 768
    __shared__ float sGi[16*144];     // 2304
    __shared__ float sWgt[16*32];     // 512
    __shared__ float sSc[16*48];      // 768
    __shared__ float sFb[48];
    __shared__ unsigned char sBin[16*32];
    const float* h  = g_h[cur];
    float* hnew     = g_h[1-cur];
    int tid = threadIdx.x;
    int r0  = blockIdx.x * 16;                  // 512 blocks
    int k = r0 >> 9, i2b = r0 & 511, b = i2b >> 5;
    int gbase = (k*TT + t)*BN + i2b;            // lhalf/gil/wgt row base
    for (int i = tid; i < 6912; i += 256) {
        int c = i / 48, m = i % 48;
        sWr[m*145 + c] = wih[c*96 + 48 + m];
    }
    for (int i = tid; i < 512; i += 256) {
        sWgt[i] = g_wgt [gbase*NN + i];
        sBin[i] = g_bins[gbase*NN + i];
    }
    if (tid < 48) sFb[tid] = scfb[tid];
    __syncthreads();
    // phase 1: rhalf gather
    for (int out = tid; out < 768; out += 256) {
        int lr = out / 48, c = out % 48;
        float acc = sFb[c];
        const float* hwb = g_HW + b*NN*NBIN*48;
        const float* wv  = sWgt + lr*32;
        const unsigned char* bv = sBin + lr*32;
        #pragma unroll 4
        for (int n2 = 0; n2 < NN; n2++) {
            float w = wv[n2];
            if (w != 0.f) acc += w * hwb[(n2*NBIN + bv[n2])*48 + c];
        }
        sR[lr*48 + c] = acc;
    }
    __syncthreads();
    // phase 2: gi = gil + rhalf @ Wr^T   (items (cg72, lrg4): 2c x 4row)
    const float* gilp = g_gil + (long)gbase*144;
    for (int it = tid; it < 288; it += 256) {
        int cg = it % 72, lrg = it / 72;
        int rowb = lrg*4;
        float a[4][2];
        #pragma unroll
        for (int i = 0; i < 4; i++) {
            a[i][0] = gilp[(rowb+i)*144 + cg];
            a[i][1] = gilp[(rowb+i)*144 + cg + 72];
        }
        for (int m = 0; m < 48; m++) {
            float w0 = sWr[m*145 + cg], w1 = sWr[m*145 + cg + 72];
            #pragma unroll
            for (int i = 0; i < 4; i++) {
                float xv = sR[(rowb+i)*48 + m];
                a[i][0] += xv*w0; a[i][1] += xv*w1;
            }
        }
        #pragma unroll
        for (int i = 0; i < 4; i++) {
            sGi[(rowb+i)*144 + cg]      = a[i][0];
            sGi[(rowb+i)*144 + cg + 72] = a[i][1];
        }
    }
    __syncthreads();
    // phase 3: GRU elementwise + score partials
    for (int out = tid; out < 768; out += 256) {
        int lr = out / 48, c = out % 48;
        int row = r0 + lr;
        const float* gh = g_gh + row*144;
        float r  = 1.f/(1.f + expf(-(sGi[lr*144 + c]      + gh[c])));
        float z  = 1.f/(1.f + expf(-(sGi[lr*144 + 48 + c] + gh[48+c])));
        float nn = tanhf(sGi[lr*144 + 96 + c] + r*gh[96+c]);
        float hv = (1.f - z)*nn + z*h[row*48 + c];
        hnew[row*48 + c] = hv;
        sSc[lr*48 + c] = hv * scw[c];
    }
    __syncthreads();
    if (tid < 16) {
        float s = 0.f;
        #pragma unroll
        for (int c = 0; c < 48; c++) s += sSc[tid*48 + c];
        g_score[r0 + tid] += s;
    }
}

// ---------------- final ----------------
__global__ void final_kernel(const float* __restrict__ dyw,
                             const float* __restrict__ dyb,
                             const float* __restrict__ scb,
                             float* __restrict__ out, int cur) {
    const float* h = g_h[cur];
    int idx = blockIdx.x*256 + threadIdx.x;    // 663552 exact
    if (idx < KBN*80) {
        int row = idx / 80, c = idx % 80;
        float acc = dyb[c];
        const float* hr = h + row*48;
        const float* w  = dyw + c*48;
        #pragma unroll 8
        for (int hh = 0; hh < 48; hh++) acc += hr[hh]*w[hh];
        int k = row >> 9, i2 = row & 511;
        int d = c / 40, tt = c % 40;
        out[((k*TT + tt)*BN + i2)*2 + d] = acc;
    } else {
        int row = idx - KBN*80;
        out[KBN*80 + row] = g_score[row] + 40.f*scb[0];
    }
}

// ---------------- launcher ----------------
extern "C" void kernel_launch(void* const* d_in, const int* in_sizes, int n_in,
                              void* d_out, int out_size) {
    const float* hx      = (const float*)d_in[0];
    const float* cur_loc = (const float*)d_in[1];
    const float* y_path  = (const float*)d_in[2];
    const float* image   = (const float*)d_in[3];
    const float* c1w     = (const float*)d_in[4];
    const float* c1b     = (const float*)d_in[5];
    const float* c2w     = (const float*)d_in[6];
    const float* c2b     = (const float*)d_in[7];
    const float* fvw     = (const float*)d_in[8];
    const float* fvb     = (const float*)d_in[9];
    const float* scfw    = (const float*)d_in[10];
    const float* scfb    = (const float*)d_in[11];
    const float* wih     = (const float*)d_in[12];
    const float* whh     = (const float*)d_in[13];
    const float* bih     = (const float*)d_in[14];
    const float* bhh     = (const float*)d_in[15];
    const float* dyw     = (const float*)d_in[16];
    const float* dyb     = (const float*)d_in[17];
    const float* scw     = (const float*)d_in[18];
    const float* scb     = (const float*)d_in[19];

    conv1_kernel     <<<6400, 256>>>(image, c1w, c1b);
    conv2_kernel     <<<1600, 256>>>(c2w, c2b);
    transposeW_kernel<<<324,  256>>>(scfw);
    lhalf_kernel     <<<61440,256>>>(y_path, cur_loc, fvw, fvb);
    gil_kernel       <<<5120, 256>>>(wih, bih);
    bins_kernel      <<<2560, 128>>>(y_path);
    init_kernel      <<<1568, 256>>>(hx);

    int cur = 0;
    for (int t = 0; t < TT; t++) {
        stepA_kernel<<<272, 256>>>(whh, bhh, cur);
        stepB_kernel<<<512, 256>>>(wih, scfb, scw, t, cur);
        cur ^= 1;
    }
    final_kernel<<<2592, 256>>>(dyw, dyb, scb, (float*)d_out, cur);
}

// round 5
// speedup vs baseline: 4.2453x; 1.0004x over previous
#include <cuda_runtime.h>
#include <math.h>

// ---------------- problem constants ----------------
#define KK   16
#define TT   40
#define BB   16
#define NN   32
#define BN   512            // BB*NN
#define KBN  8192           // KK*BN
#define HH2  80             // fmap H=W=80
#define C1   16
#define C2   32
#define NBIN 36

// ---------------- device scratch ----------------
__device__ float g_conv1[BB*C1*HH2*HH2];            // (b,oc,y,x)
__device__ float g_fmap [BB*HH2*HH2*C2];            // (b,y,x,c)
__device__ float g_lhalf[KK*TT*BN*48];              // first 48 of x per (kt,row)
__device__ float g_gil  [KK*TT*BN*144];             // lhalf @ Wih[:, :48]^T + bih
__device__ unsigned char g_bins[KK*TT*BN*NN];
__device__ float g_wgt  [KK*TT*BN*NN];
__device__ float g_WscfT[1728*48];
__device__ float g_HW   [BB*NN*NBIN*48];
__device__ float g_gh   [KBN*144];
__device__ float g_h    [2][KBN*48];
__device__ float g_score[KBN];

// ---------------- conv1 ----------------
__global__ void conv1_kernel(const float* __restrict__ img,
                             const float* __restrict__ w,
                             const float* __restrict__ bias) {
    __shared__ float sW[1600];
    __shared__ float sB[16];
    for (int i = threadIdx.x; i < 1600; i += 256) sW[i] = w[i];
    if (threadIdx.x < 16) sB[threadIdx.x] = bias[threadIdx.x];
    __syncthreads();
    int idx = blockIdx.x*256 + threadIdx.x;          // 1,638,400 exact
    int x = idx % HH2; int y = (idx/HH2) % HH2;
    int oc = (idx/(HH2*HH2)) % C1; int b = idx/(HH2*HH2*C1);
    float acc = sB[oc];
    for (int ic = 0; ic < 4; ic++) {
        for (int ky = 0; ky < 5; ky++) {
            int iy = 2*y - 2 + ky;
            if (iy < 0 || iy >= 160) continue;
            const float* ip = img + ((b*4+ic)*160 + iy)*160;
            const float* wp = sW + (oc*4+ic)*25 + ky*5;
            #pragma unroll
            for (int kx = 0; kx < 5; kx++) {
                int ix = 2*x - 2 + kx;
                if (ix < 0 || ix >= 160) continue;
                acc += ip[ix] * wp[kx];
            }
        }
    }
    g_conv1[idx] = fmaxf(acc, 0.f);
}

// ---------------- conv2 ----------------
__global__ void conv2_kernel(const float* __restrict__ w2,
                             const float* __restrict__ b2) {
    __shared__ float sIn[16*20*20];
    __shared__ float sW [8*16*25];
    int blk = blockIdx.x;                       // 1600
    int ocg = blk % 4; int tile = (blk/4) % 25; int b = blk/100;
    int ty0 = (tile/5)*16, tx0 = (tile%5)*16;
    int tid = threadIdx.x;
    for (int i = tid; i < 6400; i += 256) {
        int ic = i/400; int rem = i%400; int ly = rem/20, lx = rem%20;
        int iy = ty0 + ly - 2, ix = tx0 + lx - 2;
        sIn[i] = (iy>=0 && iy<HH2 && ix>=0 && ix<HH2)
                 ? g_conv1[((b*C1+ic)*HH2+iy)*HH2+ix] : 0.f;
    }
    for (int i = tid; i < 3200; i += 256) sW[i] = w2[ocg*3200 + i];
    __syncthreads();
    int ty = tid/16, tx = tid%16;
    for (int ocl = 0; ocl < 8; ocl++) {
        int oc = ocg*8 + ocl;
        float acc = b2[oc];
        for (int ic = 0; ic < 16; ic++) {
            const float* ip = sIn + ic*400;
            const float* wp = sW + ocl*400 + ic*25;
            #pragma unroll
            for (int ky = 0; ky < 5; ky++)
                #pragma unroll
                for (int kx = 0; kx < 5; kx++)
                    acc += ip[(ty+ky)*20 + (tx+kx)] * wp[ky*5+kx];
        }
        g_fmap[((b*HH2 + ty0+ty)*HH2 + tx0+tx)*C2 + oc] = fmaxf(acc, 0.f);
    }
}

// ---------------- transpose fc_scf_w ----------------
__global__ void transposeW_kernel(const float* __restrict__ w) {
    int idx = blockIdx.x*256 + threadIdx.x;    // 82944 exact
    int c = idx / 1728; int oh = idx % 1728;
    g_WscfT[oh*48 + c] = w[idx];
}

// ---------------- lhalf (coalesced: thread = (row,c)) ----------------
__global__ void lhalf_kernel(const float* __restrict__ y_path,
                             const float* __restrict__ cur_loc,
                             const float* __restrict__ fvw,
                             const float* __restrict__ fvb) {
    int idx = blockIdx.x*256 + threadIdx.x;    // 15,728,640 exact
    int c = idx % 48; int row = idx / 48;
    int kt = row / BN, i2 = row % BN;
    int t = kt % TT; int b = i2 >> 5;
    float px = y_path[row*2], py = y_path[row*2+1];
    float out;
    if (c < 32) {
        int u = 40 - (int)py; u = min(max(u,0), HH2-1);
        int v = (int)px;      v = min(max(v,0), HH2-1);
        out = g_fmap[((b*HH2+u)*HH2+v)*C2 + c];
    } else {
        int cc = c - 32;
        float pvx, pvy;
        if (t == 0) { pvx = cur_loc[i2*2]; pvy = cur_loc[i2*2+1]; }
        else { pvx = y_path[(row-BN)*2]; pvy = y_path[(row-BN)*2+1]; }
        out = fvb[cc] + (px-pvx)*10.f*fvw[cc*2] + (py-pvy)*10.f*fvw[cc*2+1];
    }
    g_lhalf[idx] = out;
}

// ---------------- gil = lhalf @ Wih[:, :48]^T + bih ----------------
__global__ void gil_kernel(const float* __restrict__ wih,
                           const float* __restrict__ bih) {
    __shared__ float sA[64*48];     // 3072
    __shared__ float sW[48*145];    // 6960 (transposed, padded odd)
    __shared__ float sB[144];
    int tid = threadIdx.x;
    int r0 = blockIdx.x * 64;                   // 5120 blocks
    for (int i = tid; i < 3072; i += 256) sA[i] = g_lhalf[r0*48 + i];
    for (int i = tid; i < 6912; i += 256) {
        int c = i / 48, m = i % 48;
        sW[m*145 + c] = wih[c*96 + m];
    }
    if (tid < 144) sB[tid] = bih[tid];
    __syncthreads();
    for (int it = tid; it < 576; it += 256) {   // (cg36, lrg16), 4c x 4row
        int cg = it % 36, lrg = it / 36;
        float acc[4][4];
        #pragma unroll
        for (int j = 0; j < 4; j++) {
            float bv = sB[cg + 36*j];
            #pragma unroll
            for (int i = 0; i < 4; i++) acc[i][j] = bv;
        }
        for (int m = 0; m < 48; m++) {
            float av[4], wv[4];
            #pragma unroll
            for (int i = 0; i < 4; i++) av[i] = sA[(lrg*4+i)*48 + m];
            #pragma unroll
            for (int j = 0; j < 4; j++) wv[j] = sW[m*145 + cg + 36*j];
            #pragma unroll
            for (int i = 0; i < 4; i++)
                #pragma unroll
                for (int j = 0; j < 4; j++) acc[i][j] += av[i]*wv[j];
        }
        #pragma unroll
        for (int i = 0; i < 4; i++)
            #pragma unroll
            for (int j = 0; j < 4; j++)
                g_gil[(r0 + lrg*4+i)*144 + cg + 36*j] = acc[i][j];
    }
}

// ---------------- bins ----------------
__global__ void bins_kernel(const float* __restrict__ y_path) {
    __shared__ float sP[4][NN][2];
    int tid = threadIdx.x;
    int g = tid >> 5, j = tid & 31;
    int grp = blockIdx.x*4 + g;                // 10240 exact
    int b = grp % BB; int kt = grp / BB;
    int rowbase = kt*BN + b*NN;
    sP[g][j][0] = y_path[(rowbase+j)*2];
    sP[g][j][1] = y_path[(rowbase+j)*2+1];
    __syncwarp();
    float pjx = sP[g][j][0], pjy = sP[g][j][1];
    unsigned char binloc[NN];
    int cnt[NBIN];
    #pragma unroll
    for (int o = 0; o < NBIN; o++) cnt[o] = 0;
    unsigned int maskbits = 0;
    const float R_STEP  = (float)(3.5/6.0);
    const float TH_STEP = (float)(6.283185307179586/6.0);
    for (int n2 = 0; n2 < NN; n2++) {
        float dx = sP[g][n2][0] - pjx;
        float dy = sP[g][n2][1] - pjy;
        float dist = sqrtf(dx*dx + dy*dy);
        bool m = (n2 != j) && (dist >= 0.5f) && (dist <= 4.0f);
        float dc = dist < 1e-10f ? 1e-10f : dist;
        float ct = acosf(fminf(fmaxf(dx/dc, -1.f), 1.f));
        float theta = (dy < -0.01f) ? (6.2831853071795864f - ct) : ct;
        int ub = (int)((dist - 0.5f)/R_STEP); ub = min(max(ub,0),5);
        int vb = (int)(theta/TH_STEP);        vb = min(max(vb,0),5);
        int bin = ub*6 + vb;
        binloc[n2] = (unsigned char)bin;
        if (m) { maskbits |= (1u<<n2); cnt[bin]++; }
    }
    int out0 = (rowbase + j)*NN;
    for (int n2 = 0; n2 < NN; n2++) {
        bool m = (maskbits >> n2) & 1u;
        g_bins[out0+n2] = binloc[n2];
        g_wgt [out0+n2] = m ? (1.f/(float)cnt[binloc[n2]]) : 0.f;
    }
}

// ---------------- init ----------------
__global__ void init_kernel(const float* __restrict__ hx) {
    int idx = blockIdx.x*256 + threadIdx.x;    // 401408 exact
    if (idx < KBN*48) g_h[0][idx] = hx[idx % (BN*48)];
    else g_score[idx - KBN*48] = 0.f;
}

// ---------------- step A: HW table + gh (conflict-free, reg-tiled) --------
__global__ void stepA_kernel(const float* __restrict__ whh,
                             const float* __restrict__ bhh, int cur) {
    __shared__ float sm[10752];
    const float* h = g_h[cur];
    int blk = blockIdx.x, tid = threadIdx.x;
    if (blk < 144) {                            // HW: 16 b x 9 o-groups(4 each)
        float* sWT = sm;            // 192*48 = 9216
        float* sHn = sm + 9216;     // 32*48  = 1536
        int b = blk / 9, og = blk % 9;
        const float* src = g_WscfT + og*192*48;
        for (int i = tid; i < 9216; i += 256) sWT[i] = src[i];
        const float* hs = h + b*NN*48;
        for (int i = tid; i < 1536; i += 256) sHn[i] = hs[i];
        __syncthreads();
        // items (cg24, oo4, n2g8): each 2c x 4n2
        for (int it = tid; it < 768; it += 256) {
            int cg = it % 24; int oo = (it/24) & 3; int n2g = it / 96;
            float acc[4][2];
            #pragma unroll
            for (int i = 0; i < 4; i++) { acc[i][0] = 0.f; acc[i][1] = 0.f; }
            const float* wt = sWT + oo*2304;
            for (int hh = 0; hh < 48; hh++) {
                float w0 = wt[hh*48 + cg];
                float w1 = wt[hh*48 + cg + 24];
                #pragma unroll
                for (int i = 0; i < 4; i++) {
                    float hv = sHn[(n2g*4+i)*48 + hh];
                    acc[i][0] += hv*w0; acc[i][1] += hv*w1;
                }
            }
            #pragma unroll
            for (int i = 0; i < 4; i++) {
                int base = ((b*NN + n2g*4+i)*NBIN + og*4 + oo)*48;
                g_HW[base + cg]      = acc[i][0];
                g_HW[base + cg + 24] = acc[i][1];
            }
        }
    } else {                                    // gh: 128 blocks x 64 rows
        float* sW  = sm;             // 144*49 = 7056 (padded)
        float* sH  = sm + 7056;      // 3072
        float* sBh = sm + 10128;     // 144
        int r0 = (blk - 144) * 64;
        for (int i = tid; i < 6912; i += 256) sW[(i/48)*49 + (i%48)] = whh[i];
        const float* hs = h + r0*48;
        for (int i = tid; i < 3072; i += 256) sH[i] = hs[i];
        if (tid < 144) sBh[tid] = bhh[tid];
        __syncthreads();
        // items (cg36, rg16): each 4c x 4row, interleaved c
        for (int it = tid; it < 576; it += 256) {
            int cg = it % 36, rg = it / 36;
            float acc[4][4];
            #pragma unroll
            for (int j = 0; j < 4; j++) {
                float bv = sBh[cg + 36*j];
                #pragma unroll
                for (int i = 0; i < 4; i++) acc[i][j] = bv;
            }
            for (int hh = 0; hh < 48; hh++) {
                float hv[4], wv[4];
                #pragma unroll
                for (int i = 0; i < 4; i++) hv[i] = sH[(rg*4+i)*48 + hh];
                #pragma unroll
                for (int j = 0; j < 4; j++) wv[j] = sW[(cg+36*j)*49 + hh];
                #pragma unroll
                for (int i = 0; i < 4; i++)
                    #pragma unroll
                    for (int j = 0; j < 4; j++) acc[i][j] += hv[i]*wv[j];
            }
            #pragma unroll
            for (int i = 0; i < 4; i++)
                #pragma unroll
                for (int j = 0; j < 4; j++)
                    g_gh[(r0 + rg*4+i)*144 + cg + 36*j] = acc[i][j];
        }
    }
}

// ---------------- step B: rhalf + gi(+gil) + GRU + score -------------------
__global__ void stepB_kernel(const float* __restrict__ wih,
                             const float* __restrict__ scfb,
                             const float* __restrict__ scw,
                             int t, int cur) {
    __shared__ float sWr[48*145];     // 6960 (transposed r-half, padded)
    __shared__ float sR [16*48];      // 768
    __shared__ float sGi[16*144];     // 2304
    __shared__ float sWgt[16*32];     // 512
    __shared__ float sSc[16*48];      // 768
    __shared__ float sFb[48];
    __shared__ unsigned char sBin[16*32];
    const float* h  = g_h[cur];
    float* hnew     = g_h[1-cur];
    int tid = threadIdx.x;
    int r0  = blockIdx.x * 16;                  // 512 blocks
    int k = r0 >> 9, i2b = r0 & 511, b = i2b >> 5;
    int gbase = (k*TT + t)*BN + i2b;            // lhalf/gil/wgt row base
    for (int i = tid; i < 6912; i += 256) {
        int c = i / 48, m = i % 48;
        sWr[m*145 + c] = wih[c*96 + 48 + m];
    }
    for (int i = tid; i < 512; i += 256) {
        sWgt[i] = g_wgt [gbase*NN + i];
        sBin[i] = g_bins[gbase*NN + i];
    }
    if (tid < 48) sFb[tid] = scfb[tid];
    __syncthreads();
    // phase 1: rhalf gather
    for (int out = tid; out < 768; out += 256) {
        int lr = out / 48, c = out % 48;
        float acc = sFb[c];
        const float* hwb = g_HW + b*NN*NBIN*48;
        const float* wv  = sWgt + lr*32;
        const unsigned char* bv = sBin + lr*32;
        #pragma unroll 4
        for (int n2 = 0; n2 < NN; n2++) {
            float w = wv[n2];
            if (w != 0.f) acc += w * hwb[(n2*NBIN + bv[n2])*48 + c];
        }
        sR[lr*48 + c] = acc;
    }
    __syncthreads();
    // phase 2: gi = gil + rhalf @ Wr^T   (items (cg72, lrg4): 2c x 4row)
    const float* gilp = g_gil + (long)gbase*144;
    for (int it = tid; it < 288; it += 256) {
        int cg = it % 72, lrg = it / 72;
        int rowb = lrg*4;
        float a[4][2];
        #pragma unroll
        for (int i = 0; i < 4; i++) {
            a[i][0] = gilp[(rowb+i)*144 + cg];
            a[i][1] = gilp[(rowb+i)*144 + cg + 72];
        }
        for (int m = 0; m < 48; m++) {
            float w0 = sWr[m*145 + cg], w1 = sWr[m*145 + cg + 72];
            #pragma unroll
            for (int i = 0; i < 4; i++) {
                float xv = sR[(rowb+i)*48 + m];
                a[i][0] += xv*w0; a[i][1] += xv*w1;
            }
        }
        #pragma unroll
        for (int i = 0; i < 4; i++) {
            sGi[(rowb+i)*144 + cg]      = a[i][0];
            sGi[(rowb+i)*144 + cg + 72] = a[i][1];
        }
    }
    __syncthreads();
    // phase 3: GRU elementwise + score partials
    for (int out = tid; out < 768; out += 256) {
        int lr = out / 48, c = out % 48;
        int row = r0 + lr;
        const float* gh = g_gh + row*144;
        float r  = 1.f/(1.f + expf(-(sGi[lr*144 + c]      + gh[c])));
        float z  = 1.f/(1.f + expf(-(sGi[lr*144 + 48 + c] + gh[48+c])));
        float nn = tanhf(sGi[lr*144 + 96 + c] + r*gh[96+c]);
        float hv = (1.f - z)*nn + z*h[row*48 + c];
        hnew[row*48 + c] = hv;
        sSc[lr*48 + c] = hv * scw[c];
    }
    __syncthreads();
    if (tid < 16) {
        float s = 0.f;
        #pragma unroll
        for (int c = 0; c < 48; c++) s += sSc[tid*48 + c];
        g_score[r0 + tid] += s;
    }
}

// ---------------- final ----------------
__global__ void final_kernel(const float* __restrict__ dyw,
                             const float* __restrict__ dyb,
                             const float* __restrict__ scb,
                             float* __restrict__ out, int cur) {
    const float* h = g_h[cur];
    int idx = blockIdx.x*256 + threadIdx.x;    // 663552 exact
    if (idx < KBN*80) {
        int row = idx / 80, c = idx % 80;
        float acc = dyb[c];
        const float* hr = h + row*48;
        const float* w  = dyw + c*48;
        #pragma unroll 8
        for (int hh = 0; hh < 48; hh++) acc += hr[hh]*w[hh];
        int k = row >> 9, i2 = row & 511;
        int d = c / 40, tt = c % 40;
        out[((k*TT + tt)*BN + i2)*2 + d] = acc;
    } else {
        int row = idx - KBN*80;
        out[KBN*80 + row] = g_score[row] + 40.f*scb[0];
    }
}

// ---------------- launcher ----------------
extern "C" void kernel_launch(void* const* d_in, const int* in_sizes, int n_in,
                              void* d_out, int out_size) {
    const float* hx      = (const float*)d_in[0];
    const float* cur_loc = (const float*)d_in[1];
    const float* y_path  = (const float*)d_in[2];
    const float* image   = (const float*)d_in[3];
    const float* c1w     = (const float*)d_in[4];
    const float* c1b     = (const float*)d_in[5];
    const float* c2w     = (const float*)d_in[6];
    const float* c2b     = (const float*)d_in[7];
    const float* fvw     = (const float*)d_in[8];
    const float* fvb     = (const float*)d_in[9];
    const float* scfw    = (const float*)d_in[10];
    const float* scfb    = (const float*)d_in[11];
    const float* wih     = (const float*)d_in[12];
    const float* whh     = (const float*)d_in[13];
    const float* bih     = (const float*)d_in[14];
    const float* bhh     = (const float*)d_in[15];
    const float* dyw     = (const float*)d_in[16];
    const float* dyb     = (const float*)d_in[17];
    const float* scw     = (const float*)d_in[18];
    const float* scb     = (const float*)d_in[19];

    conv1_kernel     <<<6400, 256>>>(image, c1w, c1b);
    conv2_kernel     <<<1600, 256>>>(c2w, c2b);
    transposeW_kernel<<<324,  256>>>(scfw);
    lhalf_kernel     <<<61440,256>>>(y_path, cur_loc, fvw, fvb);
    gil_kernel       <<<5120, 256>>>(wih, bih);
    bins_kernel      <<<2560, 128>>>(y_path);
    init_kernel      <<<1568, 256>>>(hx);

    int cur = 0;
    for (int t = 0; t < TT; t++) {
        stepA_kernel<<<272, 256>>>(whh, bhh, cur);
        stepB_kernel<<<512, 256>>>(wih, scfb, scw, t, cur);
        cur ^= 1;
    }
    final_kernel<<<2592, 256>>>(dyw, dyb, scb, (float*)d_out, cur);
}